// round 7
// baseline (speedup 1.0000x reference)
#include <cuda_runtime.h>
#include <cuda_bf16.h>
#include <cstdint>

#define BB 8
#define CC 64
#define NN 100000
#define R3 32768  // 32^3

// Scratch: sums in [b, v, c] layout so one point's channel-adds are contiguous
// (red.global.add.v4.f32). 64MB, L2-resident during accumulation.
// NOTE: no zero_kernel — __device__ globals start zeroed at module load, and
// transpose_mean_kernel restores zeros after reading, so the invariant
// "scratch is zero at kernel_launch entry" holds across graph replays.
__device__ float g_sums[(size_t)BB * R3 * CC];
__device__ int   g_cnt[BB * R3];

// ---------------------------------------------------------------------------
// Point kernel, vectorized: each warp handles a 128-point chunk for one
// 16-channel group; each lane owns 4 consecutive points -> all loads LDG.128.
// blockDim = 256 (8 warps = 2 chunks x 4 channel-groups).
// mode: 0 = no coords output, 1 = int64 coords, 2 = float coords
__global__ void __launch_bounds__(256) point_kernel(
        const float* __restrict__ feat,
        const float* __restrict__ coords,
        char* out_coords, int mode) {
    int w     = threadIdx.x >> 5;          // warp in block (0..7)
    int lane  = threadIdx.x & 31;
    int chunk = blockIdx.x * 2 + (w >> 2); // 128-point chunk
    int g     = w & 3;                     // channel group: channels [16g, 16g+16)
    int b     = blockIdx.y;
    int n0    = chunk * 128 + lane * 4;
    if (n0 >= NN) return;                  // NN % 4 == 0: lane's 4 pts all valid or none

    const float* cb = coords + (size_t)b * 3 * NN;
    float4 x = __ldcs((const float4*)(cb + n0));
    float4 y = __ldcs((const float4*)(cb + NN + n0));
    float4 z = __ldcs((const float4*)(cb + 2 * NN + n0));

    // clip(coord*R, 0, R-1) then round-to-nearest-even (matches jnp.round)
    int vx[4], vy[4], vz[4], voxel[4];
    {
        const float* xs = &x.x; const float* ys = &y.x; const float* zs = &z.x;
#pragma unroll
        for (int i = 0; i < 4; i++) {
            vx[i] = (int)rintf(fminf(fmaxf(xs[i] * 32.f, 0.f), 31.f));
            vy[i] = (int)rintf(fminf(fmaxf(ys[i] * 32.f, 0.f), 31.f));
            vz[i] = (int)rintf(fminf(fmaxf(zs[i] * 32.f, 0.f), 31.f));
            voxel[i] = vx[i] * 1024 + vy[i] * 32 + vz[i];
        }
    }

    // Only channel-group 0 emits coords + counts (once per point).
    if (g == 0) {
        if (mode == 1) {
            long long* oc = reinterpret_cast<long long*>(out_coords) + (size_t)b * 3 * NN;
            *(longlong2*)(oc + n0)              = make_longlong2(vx[0], vx[1]);
            *(longlong2*)(oc + n0 + 2)          = make_longlong2(vx[2], vx[3]);
            *(longlong2*)(oc + NN + n0)         = make_longlong2(vy[0], vy[1]);
            *(longlong2*)(oc + NN + n0 + 2)     = make_longlong2(vy[2], vy[3]);
            *(longlong2*)(oc + 2 * NN + n0)     = make_longlong2(vz[0], vz[1]);
            *(longlong2*)(oc + 2 * NN + n0 + 2) = make_longlong2(vz[2], vz[3]);
        } else if (mode == 2) {
            float* oc = reinterpret_cast<float*>(out_coords) + (size_t)b * 3 * NN;
            *(float4*)(oc + n0)          = make_float4(vx[0], vx[1], vx[2], vx[3]);
            *(float4*)(oc + NN + n0)     = make_float4(vy[0], vy[1], vy[2], vy[3]);
            *(float4*)(oc + 2 * NN + n0) = make_float4(vz[0], vz[1], vz[2], vz[3]);
        }
#pragma unroll
        for (int i = 0; i < 4; i++)
            atomicAdd(&g_cnt[b * R3 + voxel[i]], 1);
    }

    // Load 16 channels x 4 points as LDG.128 (coalesced & vectorized), then
    // scatter-accumulate with red.global.add.v4.f32 (4 per point).
    float fv[4][16];
    const float* fb = feat + ((size_t)b * CC + g * 16) * NN + n0;
#pragma unroll
    for (int c = 0; c < 16; c++) {
        float4 t = __ldcs((const float4*)(fb + (size_t)c * NN));
        fv[0][c] = t.x; fv[1][c] = t.y; fv[2][c] = t.z; fv[3][c] = t.w;
    }
#pragma unroll
    for (int i = 0; i < 4; i++) {
        float* sb = g_sums + ((size_t)(b * R3 + voxel[i])) * CC + g * 16;
#pragma unroll
        for (int q = 0; q < 4; q++) {
            asm volatile("red.global.add.v4.f32 [%0], {%1,%2,%3,%4};"
                         :: "l"(sb + q * 4),
                            "f"(fv[i][q * 4 + 0]), "f"(fv[i][q * 4 + 1]),
                            "f"(fv[i][q * 4 + 2]), "f"(fv[i][q * 4 + 3])
                         : "memory");
        }
    }
}

// ---------------------------------------------------------------------------
// Transpose [b, v, c] -> [b, c, v] fused with the mean (x 1/max(cnt,1)),
// AND restore the scratch (sums + counts) to zero for the next replay.
// 64-voxel x 64-channel tiles via padded shared memory; both gmem sides coalesced.
__global__ void __launch_bounds__(256) transpose_mean_kernel(float* __restrict__ out) {
    __shared__ float tile[64 * 65];  // padded: conflict-free transposed reads
    __shared__ float rcp[64];

    int b   = blockIdx.y;
    int v0  = blockIdx.x * 64;
    int tid = threadIdx.x;  // 256 threads

    // Load 64 voxels x 64 channels (4096 floats) coalesced as float4,
    // zeroing each slot right after reading it (same-thread WAR, safe).
    float4* src4 = reinterpret_cast<float4*>(&g_sums[((size_t)b * R3 + v0) * CC]);
#pragma unroll
    for (int e4 = tid; e4 < 1024; e4 += 256) {
        float4 vv = src4[e4];
        src4[e4] = make_float4(0.f, 0.f, 0.f, 0.f);
        int lin = e4 * 4;
        int v = lin >> 6;
        int c = lin & 63;
        tile[v * 65 + c + 0] = vv.x;
        tile[v * 65 + c + 1] = vv.y;
        tile[v * 65 + c + 2] = vv.z;
        tile[v * 65 + c + 3] = vv.w;
    }
    if (tid < 64) {
        int cnt = g_cnt[b * R3 + v0 + tid];
        g_cnt[b * R3 + v0 + tid] = 0;
        rcp[tid] = 1.0f / fmaxf((float)cnt, 1.0f);
    }
    __syncthreads();

    // Write transposed: out[b, c, v0+vi]; streaming stores (d_out never re-read,
    // keep L2 for the resident sums of the next replay's atomics).
    float* obase = out + (size_t)b * CC * R3 + v0;
#pragma unroll
    for (int q = tid; q < 1024; q += 256) {
        int lin = q * 4;
        int c  = lin >> 6;
        int vi = lin & 63;
        float4 o;
        o.x = tile[(vi + 0) * 65 + c] * rcp[vi + 0];
        o.y = tile[(vi + 1) * 65 + c] * rcp[vi + 1];
        o.z = tile[(vi + 2) * 65 + c] * rcp[vi + 2];
        o.w = tile[(vi + 3) * 65 + c] * rcp[vi + 3];
        __stcs(reinterpret_cast<float4*>(obase + (size_t)c * R3 + vi), o);
    }
}

// ---------------------------------------------------------------------------
extern "C" void kernel_launch(void* const* d_in, const int* in_sizes, int n_in,
                              void* d_out, int out_size) {
    const float* feat   = (const float*)d_in[0];  // [B, C, N] f32
    const float* coords = (const float*)d_in[1];  // [B, 3, N] f32

    const int FEAT_ELEMS  = BB * CC * R3;   // 16,777,216
    const int COORD_ELEMS = BB * 3 * NN;    // 2,400,000

    int mode;
    if (out_size >= FEAT_ELEMS + 2 * COORD_ELEMS) {
        mode = 1;  // int64 bytes after the f32 feat block
    } else if (out_size >= FEAT_ELEMS + COORD_ELEMS) {
        mode = 2;  // coords cast to f32
    } else {
        mode = 0;  // feat only
    }
    char* out_coords = (char*)d_out + (size_t)FEAT_ELEMS * sizeof(float);

    // 1) scatter-accumulate per point (scratch is zero on entry; see note above)
    {
        const int nchunks = (NN + 127) / 128;        // 782
        dim3 grid((nchunks + 1) / 2, BB);            // 2 chunks per block
        point_kernel<<<grid, 256>>>(feat, coords, out_coords, mode);
    }
    // 2) transpose + mean into d_out, restoring scratch to zero
    {
        dim3 grid(R3 / 64, BB);
        transpose_mean_kernel<<<grid, 256>>>((float*)d_out);
    }
}

// round 8
// speedup vs baseline: 1.3737x; 1.3737x over previous
#include <cuda_runtime.h>
#include <cuda_bf16.h>
#include <cstdint>

#define BB 8
#define CC 64
#define NN 100000
#define R3 32768  // 32^3

// Scratch: sums in [b, v, c] layout so one point's channel-adds are contiguous
// (red.global.add.v4.f32). 64MB, L2-resident during accumulation.
__device__ float g_sums[(size_t)BB * R3 * CC];
__device__ int   g_cnt[BB * R3];

// ---------------------------------------------------------------------------
// Zero the scratch right BEFORE the atomics so the zeroed lines are L2-hot
// when the point kernel's REDs consume them. Grid-stride, 4 x float4/thread.
__global__ void __launch_bounds__(256) zero_kernel() {
    const int SUMS4 = (BB * R3 * CC) / 4;   // 4,194,304
    const int CNT4  = (BB * R3) / 4;        // 65,536
    const int TOTAL = SUMS4 + CNT4;         // 4,259,840
    float4 z4 = make_float4(0.f, 0.f, 0.f, 0.f);
    int stride = gridDim.x * blockDim.x;
    for (int i = blockIdx.x * blockDim.x + threadIdx.x; i < TOTAL; i += stride) {
        if (i < SUMS4) reinterpret_cast<float4*>(g_sums)[i] = z4;
        else           reinterpret_cast<int4*>(g_cnt)[i - SUMS4] = make_int4(0,0,0,0);
    }
}

// ---------------------------------------------------------------------------
// Point kernel, vectorized: each warp handles a 128-point chunk for one
// 16-channel group; each lane owns 4 consecutive points -> all loads LDG.128.
// blockDim = 256 (8 warps = 2 chunks x 4 channel-groups).
// mode: 0 = no coords output, 1 = int64 coords, 2 = float coords
__global__ void __launch_bounds__(256) point_kernel(
        const float* __restrict__ feat,
        const float* __restrict__ coords,
        char* out_coords, int mode) {
    int w     = threadIdx.x >> 5;          // warp in block (0..7)
    int lane  = threadIdx.x & 31;
    int chunk = blockIdx.x * 2 + (w >> 2); // 128-point chunk
    int g     = w & 3;                     // channel group: channels [16g, 16g+16)
    int b     = blockIdx.y;
    int n0    = chunk * 128 + lane * 4;
    if (n0 >= NN) return;                  // NN % 4 == 0: lane's 4 pts all valid or none

    const float* cb = coords + (size_t)b * 3 * NN;
    float4 x = __ldcs((const float4*)(cb + n0));
    float4 y = __ldcs((const float4*)(cb + NN + n0));
    float4 z = __ldcs((const float4*)(cb + 2 * NN + n0));

    // clip(coord*R, 0, R-1) then round-to-nearest-even (matches jnp.round)
    int vx[4], vy[4], vz[4], voxel[4];
    {
        const float* xs = &x.x; const float* ys = &y.x; const float* zs = &z.x;
#pragma unroll
        for (int i = 0; i < 4; i++) {
            vx[i] = (int)rintf(fminf(fmaxf(xs[i] * 32.f, 0.f), 31.f));
            vy[i] = (int)rintf(fminf(fmaxf(ys[i] * 32.f, 0.f), 31.f));
            vz[i] = (int)rintf(fminf(fmaxf(zs[i] * 32.f, 0.f), 31.f));
            voxel[i] = vx[i] * 1024 + vy[i] * 32 + vz[i];
        }
    }

    // Only channel-group 0 emits coords + counts (once per point).
    if (g == 0) {
        if (mode == 1) {
            long long* oc = reinterpret_cast<long long*>(out_coords) + (size_t)b * 3 * NN;
            *(longlong2*)(oc + n0)              = make_longlong2(vx[0], vx[1]);
            *(longlong2*)(oc + n0 + 2)          = make_longlong2(vx[2], vx[3]);
            *(longlong2*)(oc + NN + n0)         = make_longlong2(vy[0], vy[1]);
            *(longlong2*)(oc + NN + n0 + 2)     = make_longlong2(vy[2], vy[3]);
            *(longlong2*)(oc + 2 * NN + n0)     = make_longlong2(vz[0], vz[1]);
            *(longlong2*)(oc + 2 * NN + n0 + 2) = make_longlong2(vz[2], vz[3]);
        } else if (mode == 2) {
            float* oc = reinterpret_cast<float*>(out_coords) + (size_t)b * 3 * NN;
            *(float4*)(oc + n0)          = make_float4(vx[0], vx[1], vx[2], vx[3]);
            *(float4*)(oc + NN + n0)     = make_float4(vy[0], vy[1], vy[2], vy[3]);
            *(float4*)(oc + 2 * NN + n0) = make_float4(vz[0], vz[1], vz[2], vz[3]);
        }
#pragma unroll
        for (int i = 0; i < 4; i++)
            atomicAdd(&g_cnt[b * R3 + voxel[i]], 1);
    }

    // Load 16 channels x 4 points as LDG.128 (coalesced & vectorized), then
    // scatter-accumulate with red.global.add.v4.f32 (4 per point).
    float fv[4][16];
    const float* fb = feat + ((size_t)b * CC + g * 16) * NN + n0;
#pragma unroll
    for (int c = 0; c < 16; c++) {
        float4 t = __ldcs((const float4*)(fb + (size_t)c * NN));
        fv[0][c] = t.x; fv[1][c] = t.y; fv[2][c] = t.z; fv[3][c] = t.w;
    }
#pragma unroll
    for (int i = 0; i < 4; i++) {
        float* sb = g_sums + ((size_t)(b * R3 + voxel[i])) * CC + g * 16;
#pragma unroll
        for (int q = 0; q < 4; q++) {
            asm volatile("red.global.add.v4.f32 [%0], {%1,%2,%3,%4};"
                         :: "l"(sb + q * 4),
                            "f"(fv[i][q * 4 + 0]), "f"(fv[i][q * 4 + 1]),
                            "f"(fv[i][q * 4 + 2]), "f"(fv[i][q * 4 + 3])
                         : "memory");
        }
    }
}

// ---------------------------------------------------------------------------
// Transpose [b, v, c] -> [b, c, v] fused with the mean (x 1/max(cnt,1)).
// READ-ONLY on the scratch (no zero-restore: zeroing at end-of-replay turns
// into a DRAM round-trip because the zeros get evicted before the next
// replay's atomics; the front zero_kernel keeps them L2-hot instead).
__global__ void __launch_bounds__(256) transpose_mean_kernel(float* __restrict__ out) {
    __shared__ float tile[64 * 65];  // padded: conflict-free transposed reads
    __shared__ float rcp[64];

    int b   = blockIdx.y;
    int v0  = blockIdx.x * 64;
    int tid = threadIdx.x;  // 256 threads

    // Load 64 voxels x 64 channels (4096 floats) coalesced as float4
    const float4* src4 = reinterpret_cast<const float4*>(
        &g_sums[((size_t)b * R3 + v0) * CC]);
#pragma unroll
    for (int e4 = tid; e4 < 1024; e4 += 256) {
        float4 vv = src4[e4];
        int lin = e4 * 4;
        int v = lin >> 6;
        int c = lin & 63;
        tile[v * 65 + c + 0] = vv.x;
        tile[v * 65 + c + 1] = vv.y;
        tile[v * 65 + c + 2] = vv.z;
        tile[v * 65 + c + 3] = vv.w;
    }
    if (tid < 64) {
        int cnt = g_cnt[b * R3 + v0 + tid];
        rcp[tid] = 1.0f / fmaxf((float)cnt, 1.0f);
    }
    __syncthreads();

    // Write transposed: out[b, c, v0+vi]; streaming stores (d_out never re-read).
    float* obase = out + (size_t)b * CC * R3 + v0;
#pragma unroll
    for (int q = tid; q < 1024; q += 256) {
        int lin = q * 4;
        int c  = lin >> 6;
        int vi = lin & 63;
        float4 o;
        o.x = tile[(vi + 0) * 65 + c] * rcp[vi + 0];
        o.y = tile[(vi + 1) * 65 + c] * rcp[vi + 1];
        o.z = tile[(vi + 2) * 65 + c] * rcp[vi + 2];
        o.w = tile[(vi + 3) * 65 + c] * rcp[vi + 3];
        __stcs(reinterpret_cast<float4*>(obase + (size_t)c * R3 + vi), o);
    }
}

// ---------------------------------------------------------------------------
extern "C" void kernel_launch(void* const* d_in, const int* in_sizes, int n_in,
                              void* d_out, int out_size) {
    const float* feat   = (const float*)d_in[0];  // [B, C, N] f32
    const float* coords = (const float*)d_in[1];  // [B, 3, N] f32

    const int FEAT_ELEMS  = BB * CC * R3;   // 16,777,216
    const int COORD_ELEMS = BB * 3 * NN;    // 2,400,000

    int mode;
    if (out_size >= FEAT_ELEMS + 2 * COORD_ELEMS) {
        mode = 1;  // int64 bytes after the f32 feat block
    } else if (out_size >= FEAT_ELEMS + COORD_ELEMS) {
        mode = 2;  // coords cast to f32
    } else {
        mode = 0;  // feat only
    }
    char* out_coords = (char*)d_out + (size_t)FEAT_ELEMS * sizeof(float);

    // 1) zero scratch (immediately before atomics -> zeros stay L2-hot)
    {
        zero_kernel<<<2048, 256>>>();
    }
    // 2) scatter-accumulate per point
    {
        const int nchunks = (NN + 127) / 128;        // 782
        dim3 grid((nchunks + 1) / 2, BB);            // 2 chunks per block
        point_kernel<<<grid, 256>>>(feat, coords, out_coords, mode);
    }
    // 3) transpose + mean into d_out
    {
        dim3 grid(R3 / 64, BB);
        transpose_mean_kernel<<<grid, 256>>>((float*)d_out);
    }
}

// round 13
// speedup vs baseline: 2.0181x; 1.4691x over previous
#include <cuda_runtime.h>
#include <cuda_bf16.h>
#include <cstdint>

#define BB 8
#define CC 64
#define NN 100000
#define R3 32768  // 32^3

// Scratch: sums in [b, v, c] layout so one point's channel-adds are contiguous.
// 64MB, L2-resident during accumulation (zeroed immediately before the atomics).
__device__ float g_sums[(size_t)BB * R3 * CC];
__device__ int   g_cnt[BB * R3];

// ---------------------------------------------------------------------------
// Zero the scratch right BEFORE the atomics so the zeroed lines are L2-hot
// when the point kernel's REDs consume them. Grid-stride, float4 stores.
__global__ void __launch_bounds__(256) zero_kernel() {
    const int SUMS4 = (BB * R3 * CC) / 4;   // 4,194,304
    const int CNT4  = (BB * R3) / 4;        // 65,536
    const int TOTAL = SUMS4 + CNT4;         // 4,259,840
    float4 z4 = make_float4(0.f, 0.f, 0.f, 0.f);
    int stride = gridDim.x * blockDim.x;
    for (int i = blockIdx.x * blockDim.x + threadIdx.x; i < TOTAL; i += stride) {
        if (i < SUMS4) reinterpret_cast<float4*>(g_sums)[i] = z4;
        else           reinterpret_cast<int4*>(g_cnt)[i - SUMS4] = make_int4(0,0,0,0);
    }
}

// ---------------------------------------------------------------------------
// Point kernel with COALESCED REDs.
// Block = 256 threads handles 64 points x 64 channels of one batch.
//   Phase A (t<64): coords -> voxel index, coords output, count atomic.
//   Phase B: coalesced channel-major feature loads (LDG.128), register 4x4
//            micro-transpose, store point-major into XOR-swizzled float4 smem
//            (conflict-free stores AND reads: swizzle idx = quad ^ (p>>2)).
//   Phase C: warp-RED where lanes 0-15 = point P's 16 channel-quads (256B
//            contiguous), lanes 16-31 = point P+1 -> 4 lines per warp-RED
//            instead of 32 scattered sectors.
// mode: 0 = no coords output, 1 = int64 coords, 2 = float coords
__global__ void __launch_bounds__(256) point_kernel(
        const float* __restrict__ feat,
        const float* __restrict__ coords,
        char* out_coords, int mode) {
    __shared__ float4 s4[64 * 16];   // s4[p*16 + (q ^ (p>>2))] = channels 4q..4q+3 of point p
    __shared__ int voxel_s[64];

    int t  = threadIdx.x;
    int b  = blockIdx.y;
    int n0 = blockIdx.x * 64;
    int npts = NN - n0; if (npts > 64) npts = 64;   // 64 or 32 (NN = 1562*64 + 32)

    // ---- Phase A: voxel index + coords out + counts (threads 0..npts-1) ----
    if (t < npts) {
        const float* cb = coords + (size_t)b * 3 * NN + n0 + t;
        float x = __ldcs(cb);
        float y = __ldcs(cb + NN);
        float z = __ldcs(cb + 2 * NN);
        // clip(coord*R, 0, R-1) then round-to-nearest-even (matches jnp.round)
        int vx = (int)rintf(fminf(fmaxf(x * 32.f, 0.f), 31.f));
        int vy = (int)rintf(fminf(fmaxf(y * 32.f, 0.f), 31.f));
        int vz = (int)rintf(fminf(fmaxf(z * 32.f, 0.f), 31.f));
        int vox = vx * 1024 + vy * 32 + vz;
        voxel_s[t] = vox;
        atomicAdd(&g_cnt[b * R3 + vox], 1);
        if (mode == 1) {
            long long* oc = reinterpret_cast<long long*>(out_coords) + (size_t)b * 3 * NN + n0 + t;
            oc[0]        = (long long)vx;
            oc[NN]       = (long long)vy;
            oc[2 * NN]   = (long long)vz;
        } else if (mode == 2) {
            float* oc = reinterpret_cast<float*>(out_coords) + (size_t)b * 3 * NN + n0 + t;
            oc[0]      = (float)vx;
            oc[NN]     = (float)vy;
            oc[2 * NN] = (float)vz;
        }
    }

    // ---- Phase B: coalesced loads + transpose into swizzled smem ----
    int a  = t >> 4;   // channel quad 0..15 (channels 4a..4a+3)
    int bq = t & 15;   // point quad 0..15   (points 4bq..4bq+3)
    if (bq * 4 < npts) {
        const float* fb = feat + ((size_t)b * CC + a * 4) * NN + n0 + bq * 4;
        float4 r0 = __ldcs((const float4*)(fb));
        float4 r1 = __ldcs((const float4*)(fb + NN));
        float4 r2 = __ldcs((const float4*)(fb + 2 * (size_t)NN));
        float4 r3 = __ldcs((const float4*)(fb + 3 * (size_t)NN));
        int sw = a ^ bq;   // (p>>2) == bq for all 4 points of this quad
        s4[(bq * 4 + 0) * 16 + sw] = make_float4(r0.x, r1.x, r2.x, r3.x);
        s4[(bq * 4 + 1) * 16 + sw] = make_float4(r0.y, r1.y, r2.y, r3.y);
        s4[(bq * 4 + 2) * 16 + sw] = make_float4(r0.z, r1.z, r2.z, r3.z);
        s4[(bq * 4 + 3) * 16 + sw] = make_float4(r0.w, r1.w, r2.w, r3.w);
    }
    __syncthreads();

    // ---- Phase C: coalesced vector REDs (16 lanes = one point's 256B) ----
#pragma unroll
    for (int k = 0; k < 4; k++) {
        int idx = k * 256 + t;
        int p = idx >> 4;      // point 0..63 (16 consecutive lanes share p)
        int q = idx & 15;      // channel quad
        if (p < npts) {
            float4 v = s4[p * 16 + (q ^ (p >> 2))];
            float* dst = g_sums + ((size_t)(b * R3 + voxel_s[p])) * CC + q * 4;
            asm volatile("red.global.add.v4.f32 [%0], {%1,%2,%3,%4};"
                         :: "l"(dst), "f"(v.x), "f"(v.y), "f"(v.z), "f"(v.w)
                         : "memory");
        }
    }
}

// ---------------------------------------------------------------------------
// Transpose [b, v, c] -> [b, c, v] fused with the mean (x 1/max(cnt,1)).
// READ-ONLY on the scratch (end-of-replay zero-restore regressed: zeros got
// evicted to DRAM before the next replay's atomics; front zero_kernel instead).
__global__ void __launch_bounds__(256) transpose_mean_kernel(float* __restrict__ out) {
    __shared__ float tile[64 * 65];  // padded: conflict-free transposed reads
    __shared__ float rcp[64];

    int b   = blockIdx.y;
    int v0  = blockIdx.x * 64;
    int tid = threadIdx.x;  // 256 threads

    const float4* src4 = reinterpret_cast<const float4*>(
        &g_sums[((size_t)b * R3 + v0) * CC]);
#pragma unroll
    for (int e4 = tid; e4 < 1024; e4 += 256) {
        float4 vv = src4[e4];
        int lin = e4 * 4;
        int v = lin >> 6;
        int c = lin & 63;
        tile[v * 65 + c + 0] = vv.x;
        tile[v * 65 + c + 1] = vv.y;
        tile[v * 65 + c + 2] = vv.z;
        tile[v * 65 + c + 3] = vv.w;
    }
    if (tid < 64) {
        int cnt = g_cnt[b * R3 + v0 + tid];
        rcp[tid] = 1.0f / fmaxf((float)cnt, 1.0f);
    }
    __syncthreads();

    float* obase = out + (size_t)b * CC * R3 + v0;
#pragma unroll
    for (int q = tid; q < 1024; q += 256) {
        int lin = q * 4;
        int c  = lin >> 6;
        int vi = lin & 63;
        float4 o;
        o.x = tile[(vi + 0) * 65 + c] * rcp[vi + 0];
        o.y = tile[(vi + 1) * 65 + c] * rcp[vi + 1];
        o.z = tile[(vi + 2) * 65 + c] * rcp[vi + 2];
        o.w = tile[(vi + 3) * 65 + c] * rcp[vi + 3];
        __stcs(reinterpret_cast<float4*>(obase + (size_t)c * R3 + vi), o);
    }
}

// ---------------------------------------------------------------------------
extern "C" void kernel_launch(void* const* d_in, const int* in_sizes, int n_in,
                              void* d_out, int out_size) {
    const float* feat   = (const float*)d_in[0];  // [B, C, N] f32
    const float* coords = (const float*)d_in[1];  // [B, 3, N] f32

    const int FEAT_ELEMS  = BB * CC * R3;   // 16,777,216
    const int COORD_ELEMS = BB * 3 * NN;    // 2,400,000

    int mode;
    if (out_size >= FEAT_ELEMS + 2 * COORD_ELEMS) {
        mode = 1;  // int64 bytes after the f32 feat block
    } else if (out_size >= FEAT_ELEMS + COORD_ELEMS) {
        mode = 2;  // coords cast to f32
    } else {
        mode = 0;  // feat only
    }
    char* out_coords = (char*)d_out + (size_t)FEAT_ELEMS * sizeof(float);

    // 1) zero scratch (immediately before atomics -> zeros stay L2-hot)
    zero_kernel<<<2048, 256>>>();

    // 2) scatter-accumulate per point (coalesced vector REDs)
    {
        dim3 grid((NN + 63) / 64, BB);   // 1563 x 8
        point_kernel<<<grid, 256>>>(feat, coords, out_coords, mode);
    }
    // 3) transpose + mean into d_out
    {
        dim3 grid(R3 / 64, BB);
        transpose_mean_kernel<<<grid, 256>>>((float*)d_out);
    }
}